// round 16
// baseline (speedup 1.0000x reference)
#include <cuda_runtime.h>
#include <cuda_fp16.h>
#include <cstdint>

#define N_NODES 50000
#define N_PAD 50048              // padded row count for unpredicated staging
#define E_EDGES 800000
#define CIN_ 32
#define COUT_ 64
#define KK 25
#define RDIM 832                 // 26 * 32  (25 spline kernels + 1 root slot)
#define RW 416                   // words per z row (fp16 pairs)
#define TILE_M 128
#define N_TILES ((N_NODES + TILE_M - 1) / TILE_M)   // 391
#define KCHUNK 64                // K elements per chunk
#define KW 32                    // words per chunk row
#define CHUNKS (RDIM / KCHUNK)   // 13
#define P 36                     // smem row pitch (words)
#define NWT (COUT_ * RW)         // 26624 weight words
#define CAP 96                   // slots per node (max deg ~45 @ Poisson(16); P(>96)<1e-30)

// ---- scratch (static device globals; no allocation) ----
__device__ int      g_cntp[N_NODES * 8];           // per-node edge count, stride-8 (32B sectors)
__device__ float4   g_slots[(size_t)N_NODES * CAP];// per-node edge records {col, fx, fy, base}
__device__ uint32_t g_zh[(size_t)N_PAD * RW];      // z as fp16 pairs, 83 MB
__device__ uint32_t g_wth[NWT];                    // Wfull^T fp16 pairs [64][416]

__device__ __forceinline__ uint32_t pack_h2(float a, float b) {
    __half2 h = __floats2half2_rn(a, b);
    return *(uint32_t*)&h;
}

// ---------------- init: zero counters + prep Wfull^T fp16 ----------------
__global__ void k_init(const float* __restrict__ weight, const float* __restrict__ root) {
    int i = blockIdx.x * blockDim.x + threadIdx.x;
    if (i < N_NODES) g_cntp[i * 8] = 0;
    if (i < NWT) {
        int o = i / RW, j = i - o * RW;
        int r0 = 2 * j, r1 = 2 * j + 1;
        float w0 = (r0 < 800) ? weight[r0 * COUT_ + o] : root[(r0 - 800) * COUT_ + o];
        float w1 = (r1 < 800) ? weight[r1 * COUT_ + o] : root[(r1 - 800) * COUT_ + o];
        g_wth[i] = pack_h2(w0, w1);
    }
}

// ---------------- scatter: count + append in one pass ----------------
__global__ void k_scatter(const int* __restrict__ ei,
                          const float* __restrict__ pseudo) {
    int e = blockIdx.x * blockDim.x + threadIdx.x;
    if (e < E_EDGES) {
        int row = ei[e];
        int col = ei[E_EDGES + e];
        row = min(max(row, 0), N_NODES - 1);
        col = min(max(col, 0), N_NODES - 1);
        float vx = pseudo[2 * e]     * 4.0f;   // (KS - DEGREE) = 4
        float vy = pseudo[2 * e + 1] * 4.0f;
        float flx = floorf(vx), fly = floorf(vy);
        float fx = vx - flx, fy = vy - fly;
        int lox = min(max((int)flx, 0), 3);
        int loy = min(max((int)fly, 0), 3);
        int base = lox + 5 * loy;
        int pos = atomicAdd(&g_cntp[row * 8], 1);
        if (pos < CAP)
            g_slots[(size_t)row * CAP + pos] =
                make_float4(__int_as_float(col), fx, fy, __int_as_float(base));
    }
}

// ---------------- per-node z accumulation: registers + uniform switch ----------------
// each lane owns channel `lane`; z[25] in registers; base is warp-uniform
#define ZUPD(B) \
    z[B] += gxgy; z[(B) + 1] += fxgy; z[(B) + 5] += gxfy; z[(B) + 6] += fxfy; break;

__device__ __forceinline__ void zupdate(float* z, int b, float xv, float fx, float fy) {
    float gx = 1.0f - fx, gy = 1.0f - fy;
    float gxgy = gx * gy * xv;
    float fxgy = fx * gy * xv;
    float gxfy = gx * fy * xv;
    float fxfy = fx * fy * xv;
    switch (b) {
        case 0:  ZUPD(0)
        case 1:  ZUPD(1)
        case 2:  ZUPD(2)
        case 3:  ZUPD(3)
        case 5:  ZUPD(5)
        case 6:  ZUPD(6)
        case 7:  ZUPD(7)
        case 8:  ZUPD(8)
        case 10: ZUPD(10)
        case 11: ZUPD(11)
        case 12: ZUPD(12)
        case 13: ZUPD(13)
        case 15: ZUPD(15)
        case 16: ZUPD(16)
        case 17: ZUPD(17)
        case 18: ZUPD(18)
        default: break;
    }
}

__global__ __launch_bounds__(256) void k_accum(const float* __restrict__ x) {
    int w = threadIdx.x >> 5, lane = threadIdx.x & 31;
    int n = blockIdx.x * 8 + w;
    if (n >= N_NODES) return;

    float z[KK];
    #pragma unroll
    for (int k = 0; k < KK; ++k) z[k] = 0.0f;

    int cnt = g_cntp[n * 8];
    int deg = cnt;
    cnt = min(cnt, CAP);
    const float4* slots = &g_slots[(size_t)n * CAP];
    int e = 0;
    for (; e + 4 <= cnt; e += 4) {
        float4 e0 = slots[e];
        float4 e1 = slots[e + 1];
        float4 e2 = slots[e + 2];
        float4 e3 = slots[e + 3];
        float x0 = x[__float_as_int(e0.x) * CIN_ + lane];
        float x1 = x[__float_as_int(e1.x) * CIN_ + lane];
        float x2 = x[__float_as_int(e2.x) * CIN_ + lane];
        float x3 = x[__float_as_int(e3.x) * CIN_ + lane];
        zupdate(z, __float_as_int(e0.w), x0, e0.y, e0.z);
        zupdate(z, __float_as_int(e1.w), x1, e1.y, e1.z);
        zupdate(z, __float_as_int(e2.w), x2, e2.y, e2.z);
        zupdate(z, __float_as_int(e3.w), x3, e3.y, e3.z);
    }
    for (; e < cnt; ++e) {
        float4 ed = slots[e];
        float xv = x[__float_as_int(ed.x) * CIN_ + lane];
        zupdate(z, __float_as_int(ed.w), xv, ed.y, ed.z);
    }

    float inv = 1.0f / fmaxf((float)deg, 1.0f);
    #pragma unroll
    for (int k = 0; k < KK; ++k) z[k] *= inv;

    // writeback: word k*16+l packs channels (2l, 2l+1) of bin k
    size_t zb = (size_t)n * RW;
    int s0 = (lane * 2) & 31, s1 = (lane * 2 + 1) & 31;
    #pragma unroll
    for (int k = 0; k < KK; ++k) {
        float v0 = __shfl_sync(0xffffffffu, z[k], s0);
        float v1 = __shfl_sync(0xffffffffu, z[k], s1);
        if (lane < 16) g_zh[zb + k * 16 + lane] = pack_h2(v0, v1);
    }
    if (lane < 16)                                 // root slot: raw x
        g_zh[zb + 400 + lane] = pack_h2(x[n * CIN_ + 2 * lane],
                                        x[n * CIN_ + 2 * lane + 1]);
}

// ---------------- GEMM: fp16 A x fp16 B, cp.async + ldmatrix, 4x2 warp grid ----------------
#define ST_A  0
#define ST_B (128 * P)
#define STAGE_WORDS ((128 + 64) * P)             // 6912
#define SM_BYTES (2 * STAGE_WORDS * 4)           // 55296

#define CP16(dst, src) asm volatile("cp.async.cg.shared.global [%0], [%1], 16;" :: "r"(dst), "l"(src))
#define CP_COMMIT()    asm volatile("cp.async.commit_group;" ::: "memory")
#define CP_WAIT(n)     asm volatile("cp.async.wait_group %0;" :: "n"(n) : "memory")

__device__ __forceinline__ void mma_f16(float* c, const uint32_t* a, const uint32_t* b) {
    asm volatile(
        "mma.sync.aligned.m16n8k16.row.col.f32.f16.f16.f32 "
        "{%0,%1,%2,%3}, {%4,%5,%6,%7}, {%8,%9}, {%0,%1,%2,%3};"
        : "+f"(c[0]), "+f"(c[1]), "+f"(c[2]), "+f"(c[3])
        : "r"(a[0]), "r"(a[1]), "r"(a[2]), "r"(a[3]), "r"(b[0]), "r"(b[1]));
}

__device__ __forceinline__ void ldsm4(uint32_t* r, uint32_t addr) {
    asm volatile("ldmatrix.sync.aligned.m8n8.x4.shared.b16 {%0,%1,%2,%3}, [%4];"
                 : "=r"(r[0]), "=r"(r[1]), "=r"(r[2]), "=r"(r[3]) : "r"(addr));
}

__global__ __launch_bounds__(256) void k_gemm_mma(const float* __restrict__ bias,
                                                  float* __restrict__ out) {
    extern __shared__ uint32_t smu[];
    int tid = threadIdx.x, w = tid >> 5, lane = tid & 31;
    int n0 = blockIdx.x * TILE_M;
    int qr = lane >> 2, qc = lane & 3;
    int wm = w >> 1, wn = w & 1;     // warp grid: 4 M-groups (32 rows) x 2 N-groups (32 cols)

    uint32_t sm_base = (uint32_t)__cvta_generic_to_shared(smu);

    int a_off = ST_A + (wm * 32 + (lane & 15)) * P + ((lane >> 4) << 2);
    int b_row = ((lane >> 4) << 3) + (lane & 7);
    int b_col = (((lane >> 3) & 1) << 2);
    int b_off = ST_B + (wn * 32 + b_row) * P + b_col;

    float acc[2][4][4];
    #pragma unroll
    for (int am = 0; am < 2; ++am)
        #pragma unroll
        for (int bn = 0; bn < 4; ++bn)
            #pragma unroll
            for (int i = 0; i < 4; ++i) acc[am][bn][i] = 0.0f;

    auto stage = [&](int ch, int s) {
        int w0 = ch * KW;
        uint32_t base = sm_base + (uint32_t)(s * STAGE_WORDS) * 4u;
        #pragma unroll
        for (int it = 0; it < 4; ++it) {         // A: 128 rows x 8 uint4
            int idx = it * 256 + tid;
            int row = idx >> 3, q = idx & 7;
            const uint32_t* src = &g_zh[(size_t)(n0 + row) * RW + w0 + q * 4];
            CP16(base + (uint32_t)(ST_A + row * P + q * 4) * 4u, src);
        }
        #pragma unroll
        for (int it = 0; it < 2; ++it) {         // B: 64 rows x 8 uint4
            int idx = it * 256 + tid;
            int row = idx >> 3, q = idx & 7;
            CP16(base + (uint32_t)(ST_B + row * P + q * 4) * 4u, &g_wth[row * RW + w0 + q * 4]);
        }
        CP_COMMIT();
    };

    stage(0, 0);

    for (int ch = 0; ch < CHUNKS; ++ch) {
        if (ch + 1 < CHUNKS) {
            stage(ch + 1, (ch + 1) & 1);
            CP_WAIT(1);
        } else {
            CP_WAIT(0);
        }
        __syncthreads();

        uint32_t sbase = sm_base + (uint32_t)((ch & 1) * STAGE_WORDS) * 4u;

        #pragma unroll
        for (int ks = 0; ks < KW / 8; ++ks) {
            uint32_t kw4 = (uint32_t)(ks * 8) * 4u;
            uint32_t a[8], b[8];
            ldsm4(a,     sbase + (uint32_t)a_off * 4u + kw4);
            ldsm4(a + 4, sbase + (uint32_t)(a_off + 16 * P) * 4u + kw4);
            ldsm4(b,     sbase + (uint32_t)b_off * 4u + kw4);
            ldsm4(b + 4, sbase + (uint32_t)(b_off + 16 * P) * 4u + kw4);
            #pragma unroll
            for (int am = 0; am < 2; ++am)
                #pragma unroll
                for (int bn = 0; bn < 4; ++bn)
                    mma_f16(acc[am][bn], a + am * 4, b + bn * 2);
        }
        __syncthreads();
    }

    #pragma unroll
    for (int am = 0; am < 2; ++am) {
        int rowa = n0 + wm * 32 + am * 16 + qr;
        int rowb = rowa + 8;
        #pragma unroll
        for (int bn = 0; bn < 4; ++bn) {
            int col = wn * 32 + bn * 8 + 2 * qc;
            float b0 = bias[col], b1 = bias[col + 1];
            if (rowa < N_NODES)
                *(float2*)&out[rowa * COUT_ + col] =
                    make_float2(acc[am][bn][0] + b0, acc[am][bn][1] + b1);
            if (rowb < N_NODES)
                *(float2*)&out[rowb * COUT_ + col] =
                    make_float2(acc[am][bn][2] + b0, acc[am][bn][3] + b1);
        }
    }
}

// ---------------- launch ----------------
extern "C" void kernel_launch(void* const* d_in, const int* in_sizes, int n_in,
                              void* d_out, int out_size) {
    const float* x      = (const float*)d_in[0];
    const int*   ei     = (const int*)d_in[1];      // JAX x64-disabled: int32
    const float* pseudo = (const float*)d_in[2];
    const float* weight = (const float*)d_in[3];
    const float* root   = (const float*)d_in[4];
    const float* bias   = (const float*)d_in[5];
    float*       out    = (float*)d_out;

    static bool attr_done = false;
    if (!attr_done) {
        cudaFuncSetAttribute(k_gemm_mma, cudaFuncAttributeMaxDynamicSharedMemorySize, SM_BYTES);
        attr_done = true;
    }

    k_init    <<<(N_NODES + 255) / 256, 256>>>(weight, root);
    k_scatter <<<(E_EDGES + 255) / 256, 256>>>(ei, pseudo);
    k_accum   <<<(N_NODES + 7) / 8, 256>>>(x);
    k_gemm_mma<<<N_TILES, 256, SM_BYTES>>>(bias, out);
}

// round 17
// speedup vs baseline: 1.1045x; 1.1045x over previous
#include <cuda_runtime.h>
#include <cuda_fp16.h>
#include <cstdint>

#define N_NODES 50000
#define N_PAD 50048              // padded row count for unpredicated staging
#define E_EDGES 800000
#define CIN_ 32
#define COUT_ 64
#define KK 25
#define RDIM 832                 // 26 * 32  (25 spline kernels + 1 root slot)
#define RW 416                   // words per z row (fp16 pairs)
#define TILE_M 128
#define N_TILES ((N_NODES + TILE_M - 1) / TILE_M)   // 391
#define KCHUNK 64                // K elements per chunk
#define KW 32                    // words per chunk row
#define CHUNKS (RDIM / KCHUNK)   // 13
#define P 36                     // smem row pitch (words)
#define NWT (COUT_ * RW)         // 26624 weight words
#define CAP 96                   // slots per node (max deg ~45 @ Poisson(16); P(>96)<1e-30)

// ---- scratch (static device globals; no allocation) ----
__device__ int      g_cntp[N_NODES * 8];           // per-node edge count, stride-8 (32B sectors)
__device__ float4   g_slots[(size_t)N_NODES * CAP];// per-node edge records {col, fx, fy, base}
__device__ uint32_t g_zh[(size_t)N_PAD * RW];      // z as fp16 pairs, 83 MB
__device__ uint32_t g_wth[NWT];                    // Wfull^T fp16 pairs [64][416]

__device__ __forceinline__ uint32_t pack_h2(float a, float b) {
    __half2 h = __floats2half2_rn(a, b);
    return *(uint32_t*)&h;
}

// ---------------- init: zero counters + prep Wfull^T fp16 ----------------
__global__ void k_init(const float* __restrict__ weight, const float* __restrict__ root) {
    int i = blockIdx.x * blockDim.x + threadIdx.x;
    if (i < N_NODES) g_cntp[i * 8] = 0;
    if (i < NWT) {
        int o = i / RW, j = i - o * RW;
        int r0 = 2 * j, r1 = 2 * j + 1;
        float w0 = (r0 < 800) ? weight[r0 * COUT_ + o] : root[(r0 - 800) * COUT_ + o];
        float w1 = (r1 < 800) ? weight[r1 * COUT_ + o] : root[(r1 - 800) * COUT_ + o];
        g_wth[i] = pack_h2(w0, w1);
    }
}

// ---------------- scatter: count + append in one pass ----------------
__global__ void k_scatter(const int* __restrict__ ei,
                          const float* __restrict__ pseudo) {
    int e = blockIdx.x * blockDim.x + threadIdx.x;
    if (e < E_EDGES) {
        int row = ei[e];
        int col = ei[E_EDGES + e];
        row = min(max(row, 0), N_NODES - 1);
        col = min(max(col, 0), N_NODES - 1);
        float vx = pseudo[2 * e]     * 4.0f;   // (KS - DEGREE) = 4
        float vy = pseudo[2 * e + 1] * 4.0f;
        float flx = floorf(vx), fly = floorf(vy);
        float fx = vx - flx, fy = vy - fly;
        int lox = min(max((int)flx, 0), 3);
        int loy = min(max((int)fly, 0), 3);
        int base = lox + 5 * loy;
        int pos = atomicAdd(&g_cntp[row * 8], 1);
        if (pos < CAP)
            g_slots[(size_t)row * CAP + pos] =
                make_float4(__int_as_float(col), fx, fy, __int_as_float(base));
    }
}

// ---------------- per-node z accumulation: float2 channel pairs, 16 active lanes ----------------
__global__ __launch_bounds__(256) void k_accum(const float* __restrict__ x) {
    __shared__ float2 zsh[8][KK * 16];
    int w = threadIdx.x >> 5, lane = threadIdx.x & 31;
    int n = blockIdx.x * 8 + w;
    if (n >= N_NODES) return;
    int l = lane & 15;
    bool act = lane < 16;

    if (act) {
        #pragma unroll
        for (int k = 0; k < KK; ++k) zsh[w][k * 16 + l] = make_float2(0.0f, 0.0f);
    }
    // lane-owned slots within a warp-private region: no sync needed

    int cnt = g_cntp[n * 8];
    int deg = cnt;
    cnt = min(cnt, CAP);
    const float4* slots = &g_slots[(size_t)n * CAP];
    const float2* x2 = (const float2*)x;
    float2* zr = zsh[w];

    int e = 0;
    for (; e + 4 <= cnt; e += 4) {
        float4 e0 = slots[e];
        float4 e1 = slots[e + 1];
        float4 e2 = slots[e + 2];
        float4 e3 = slots[e + 3];
        if (act) {
            float2 x0 = x2[__float_as_int(e0.x) * 16 + l];
            float2 x1 = x2[__float_as_int(e1.x) * 16 + l];
            float2 x2v = x2[__float_as_int(e2.x) * 16 + l];
            float2 x3 = x2[__float_as_int(e3.x) * 16 + l];
            {
                int b = __float_as_int(e0.w); float fx = e0.y, fy = e0.z;
                float gx = 1.0f - fx, gy = 1.0f - fy;
                float c00 = gx * gy, c01 = fx * gy, c10 = gx * fy, c11 = fx * fy;
                float2 t;
                t = zr[(b    ) * 16 + l]; t.x += c00 * x0.x; t.y += c00 * x0.y; zr[(b    ) * 16 + l] = t;
                t = zr[(b + 1) * 16 + l]; t.x += c01 * x0.x; t.y += c01 * x0.y; zr[(b + 1) * 16 + l] = t;
                t = zr[(b + 5) * 16 + l]; t.x += c10 * x0.x; t.y += c10 * x0.y; zr[(b + 5) * 16 + l] = t;
                t = zr[(b + 6) * 16 + l]; t.x += c11 * x0.x; t.y += c11 * x0.y; zr[(b + 6) * 16 + l] = t;
            }
            {
                int b = __float_as_int(e1.w); float fx = e1.y, fy = e1.z;
                float gx = 1.0f - fx, gy = 1.0f - fy;
                float c00 = gx * gy, c01 = fx * gy, c10 = gx * fy, c11 = fx * fy;
                float2 t;
                t = zr[(b    ) * 16 + l]; t.x += c00 * x1.x; t.y += c00 * x1.y; zr[(b    ) * 16 + l] = t;
                t = zr[(b + 1) * 16 + l]; t.x += c01 * x1.x; t.y += c01 * x1.y; zr[(b + 1) * 16 + l] = t;
                t = zr[(b + 5) * 16 + l]; t.x += c10 * x1.x; t.y += c10 * x1.y; zr[(b + 5) * 16 + l] = t;
                t = zr[(b + 6) * 16 + l]; t.x += c11 * x1.x; t.y += c11 * x1.y; zr[(b + 6) * 16 + l] = t;
            }
            {
                int b = __float_as_int(e2.w); float fx = e2.y, fy = e2.z;
                float gx = 1.0f - fx, gy = 1.0f - fy;
                float c00 = gx * gy, c01 = fx * gy, c10 = gx * fy, c11 = fx * fy;
                float2 t;
                t = zr[(b    ) * 16 + l]; t.x += c00 * x2v.x; t.y += c00 * x2v.y; zr[(b    ) * 16 + l] = t;
                t = zr[(b + 1) * 16 + l]; t.x += c01 * x2v.x; t.y += c01 * x2v.y; zr[(b + 1) * 16 + l] = t;
                t = zr[(b + 5) * 16 + l]; t.x += c10 * x2v.x; t.y += c10 * x2v.y; zr[(b + 5) * 16 + l] = t;
                t = zr[(b + 6) * 16 + l]; t.x += c11 * x2v.x; t.y += c11 * x2v.y; zr[(b + 6) * 16 + l] = t;
            }
            {
                int b = __float_as_int(e3.w); float fx = e3.y, fy = e3.z;
                float gx = 1.0f - fx, gy = 1.0f - fy;
                float c00 = gx * gy, c01 = fx * gy, c10 = gx * fy, c11 = fx * fy;
                float2 t;
                t = zr[(b    ) * 16 + l]; t.x += c00 * x3.x; t.y += c00 * x3.y; zr[(b    ) * 16 + l] = t;
                t = zr[(b + 1) * 16 + l]; t.x += c01 * x3.x; t.y += c01 * x3.y; zr[(b + 1) * 16 + l] = t;
                t = zr[(b + 5) * 16 + l]; t.x += c10 * x3.x; t.y += c10 * x3.y; zr[(b + 5) * 16 + l] = t;
                t = zr[(b + 6) * 16 + l]; t.x += c11 * x3.x; t.y += c11 * x3.y; zr[(b + 6) * 16 + l] = t;
            }
        }
    }
    for (; e < cnt; ++e) {
        float4 ed = slots[e];
        if (act) {
            float2 xv = x2[__float_as_int(ed.x) * 16 + l];
            int b = __float_as_int(ed.w); float fx = ed.y, fy = ed.z;
            float gx = 1.0f - fx, gy = 1.0f - fy;
            float c00 = gx * gy, c01 = fx * gy, c10 = gx * fy, c11 = fx * fy;
            float2 t;
            t = zr[(b    ) * 16 + l]; t.x += c00 * xv.x; t.y += c00 * xv.y; zr[(b    ) * 16 + l] = t;
            t = zr[(b + 1) * 16 + l]; t.x += c01 * xv.x; t.y += c01 * xv.y; zr[(b + 1) * 16 + l] = t;
            t = zr[(b + 5) * 16 + l]; t.x += c10 * xv.x; t.y += c10 * xv.y; zr[(b + 5) * 16 + l] = t;
            t = zr[(b + 6) * 16 + l]; t.x += c11 * xv.x; t.y += c11 * xv.y; zr[(b + 6) * 16 + l] = t;
        }
    }

    if (act) {
        float inv = 1.0f / fmaxf((float)deg, 1.0f);
        size_t zb = (size_t)n * RW;
        #pragma unroll
        for (int k = 0; k < KK; ++k) {
            float2 v = zr[k * 16 + l];
            g_zh[zb + k * 16 + l] = pack_h2(v.x * inv, v.y * inv);
        }
        float2 xr = x2[n * 16 + l];                // root slot: raw x
        g_zh[zb + 400 + l] = pack_h2(xr.x, xr.y);
    }
}

// ---------------- GEMM: fp16 A x fp16 B, cp.async + ldmatrix, 4x2 warp grid ----------------
#define ST_A  0
#define ST_B (128 * P)
#define STAGE_WORDS ((128 + 64) * P)             // 6912
#define SM_BYTES (2 * STAGE_WORDS * 4)           // 55296

#define CP16(dst, src) asm volatile("cp.async.cg.shared.global [%0], [%1], 16;" :: "r"(dst), "l"(src))
#define CP_COMMIT()    asm volatile("cp.async.commit_group;" ::: "memory")
#define CP_WAIT(n)     asm volatile("cp.async.wait_group %0;" :: "n"(n) : "memory")

__device__ __forceinline__ void mma_f16(float* c, const uint32_t* a, const uint32_t* b) {
    asm volatile(
        "mma.sync.aligned.m16n8k16.row.col.f32.f16.f16.f32 "
        "{%0,%1,%2,%3}, {%4,%5,%6,%7}, {%8,%9}, {%0,%1,%2,%3};"
        : "+f"(c[0]), "+f"(c[1]), "+f"(c[2]), "+f"(c[3])
        : "r"(a[0]), "r"(a[1]), "r"(a[2]), "r"(a[3]), "r"(b[0]), "r"(b[1]));
}

__device__ __forceinline__ void ldsm4(uint32_t* r, uint32_t addr) {
    asm volatile("ldmatrix.sync.aligned.m8n8.x4.shared.b16 {%0,%1,%2,%3}, [%4];"
                 : "=r"(r[0]), "=r"(r[1]), "=r"(r[2]), "=r"(r[3]) : "r"(addr));
}

__global__ __launch_bounds__(256) void k_gemm_mma(const float* __restrict__ bias,
                                                  float* __restrict__ out) {
    extern __shared__ uint32_t smu[];
    int tid = threadIdx.x, w = tid >> 5, lane = tid & 31;
    int n0 = blockIdx.x * TILE_M;
    int qr = lane >> 2, qc = lane & 3;
    int wm = w >> 1, wn = w & 1;     // warp grid: 4 M-groups (32 rows) x 2 N-groups (32 cols)

    uint32_t sm_base = (uint32_t)__cvta_generic_to_shared(smu);

    int a_off = ST_A + (wm * 32 + (lane & 15)) * P + ((lane >> 4) << 2);
    int b_row = ((lane >> 4) << 3) + (lane & 7);
    int b_col = (((lane >> 3) & 1) << 2);
    int b_off = ST_B + (wn * 32 + b_row) * P + b_col;

    float acc[2][4][4];
    #pragma unroll
    for (int am = 0; am < 2; ++am)
        #pragma unroll
        for (int bn = 0; bn < 4; ++bn)
            #pragma unroll
            for (int i = 0; i < 4; ++i) acc[am][bn][i] = 0.0f;

    auto stage = [&](int ch, int s) {
        int w0 = ch * KW;
        uint32_t base = sm_base + (uint32_t)(s * STAGE_WORDS) * 4u;
        #pragma unroll
        for (int it = 0; it < 4; ++it) {         // A: 128 rows x 8 uint4
            int idx = it * 256 + tid;
            int row = idx >> 3, q = idx & 7;
            const uint32_t* src = &g_zh[(size_t)(n0 + row) * RW + w0 + q * 4];
            CP16(base + (uint32_t)(ST_A + row * P + q * 4) * 4u, src);
        }
        #pragma unroll
        for (int it = 0; it < 2; ++it) {         // B: 64 rows x 8 uint4
            int idx = it * 256 + tid;
            int row = idx >> 3, q = idx & 7;
            CP16(base + (uint32_t)(ST_B + row * P + q * 4) * 4u, &g_wth[row * RW + w0 + q * 4]);
        }
        CP_COMMIT();
    };

    stage(0, 0);

    for (int ch = 0; ch < CHUNKS; ++ch) {
        if (ch + 1 < CHUNKS) {
            stage(ch + 1, (ch + 1) & 1);
            CP_WAIT(1);
        } else {
            CP_WAIT(0);
        }
        __syncthreads();

        uint32_t sbase = sm_base + (uint32_t)((ch & 1) * STAGE_WORDS) * 4u;

        #pragma unroll
        for (int ks = 0; ks < KW / 8; ++ks) {
            uint32_t kw4 = (uint32_t)(ks * 8) * 4u;
            uint32_t a[8], b[8];
            ldsm4(a,     sbase + (uint32_t)a_off * 4u + kw4);
            ldsm4(a + 4, sbase + (uint32_t)(a_off + 16 * P) * 4u + kw4);
            ldsm4(b,     sbase + (uint32_t)b_off * 4u + kw4);
            ldsm4(b + 4, sbase + (uint32_t)(b_off + 16 * P) * 4u + kw4);
            #pragma unroll
            for (int am = 0; am < 2; ++am)
                #pragma unroll
                for (int bn = 0; bn < 4; ++bn)
                    mma_f16(acc[am][bn], a + am * 4, b + bn * 2);
        }
        __syncthreads();
    }

    #pragma unroll
    for (int am = 0; am < 2; ++am) {
        int rowa = n0 + wm * 32 + am * 16 + qr;
        int rowb = rowa + 8;
        #pragma unroll
        for (int bn = 0; bn < 4; ++bn) {
            int col = wn * 32 + bn * 8 + 2 * qc;
            float b0 = bias[col], b1 = bias[col + 1];
            if (rowa < N_NODES)
                *(float2*)&out[rowa * COUT_ + col] =
                    make_float2(acc[am][bn][0] + b0, acc[am][bn][1] + b1);
            if (rowb < N_NODES)
                *(float2*)&out[rowb * COUT_ + col] =
                    make_float2(acc[am][bn][2] + b0, acc[am][bn][3] + b1);
        }
    }
}

// ---------------- launch ----------------
extern "C" void kernel_launch(void* const* d_in, const int* in_sizes, int n_in,
                              void* d_out, int out_size) {
    const float* x      = (const float*)d_in[0];
    const int*   ei     = (const int*)d_in[1];      // JAX x64-disabled: int32
    const float* pseudo = (const float*)d_in[2];
    const float* weight = (const float*)d_in[3];
    const float* root   = (const float*)d_in[4];
    const float* bias   = (const float*)d_in[5];
    float*       out    = (float*)d_out;

    static bool attr_done = false;
    if (!attr_done) {
        cudaFuncSetAttribute(k_gemm_mma, cudaFuncAttributeMaxDynamicSharedMemorySize, SM_BYTES);
        attr_done = true;
    }

    k_init    <<<(N_NODES + 255) / 256, 256>>>(weight, root);
    k_scatter <<<(E_EDGES + 255) / 256, 256>>>(ei, pseudo);
    k_accum   <<<(N_NODES + 7) / 8, 256>>>(x);
    k_gemm_mma<<<N_TILES, 256, SM_BYTES>>>(bias, out);
}